// round 2
// baseline (speedup 1.0000x reference)
#include <cuda_runtime.h>
#include <cuda_bf16.h>
#include <cstdint>

#define N_DIM 4096
#define D_DIM 256
#define TILE  128
#define GRID_TILES (N_DIM / TILE)            // 32
#define NUM_CTAS   (GRID_TILES * GRID_TILES) // 1024

// ---------------- device scratch (no allocation allowed) ----------------
__device__ __nv_bfloat16 g_xb[N_DIM * D_DIM];   // 2 MB bf16 copy of x
__device__ float g_sq[N_DIM];                    // row squared norms (fp32 exact)
__device__ float g_partial[NUM_CTAS];            // per-CTA d2 partial sums
__device__ float g_inv;                          // 1 / (2 * sigma^2)

// ---------------- helpers ----------------
__device__ __forceinline__ uint32_t smem_to_u32(const void* p) {
    uint32_t a;
    asm("{ .reg .u64 t; cvta.to.shared.u64 t, %1; cvt.u32.u64 %0, t; }" : "=r"(a) : "l"(p));
    return a;
}

__device__ __forceinline__ void ldsm_x4(uint32_t r[4], uint32_t addr) {
    asm volatile("ldmatrix.sync.aligned.m8n8.x4.shared.b16 {%0,%1,%2,%3}, [%4];"
                 : "=r"(r[0]), "=r"(r[1]), "=r"(r[2]), "=r"(r[3]) : "r"(addr));
}

__device__ __forceinline__ void mma_16816_bf16(float c[4], const uint32_t a[4],
                                               uint32_t b0, uint32_t b1) {
    asm volatile(
        "mma.sync.aligned.m16n8k16.row.col.f32.bf16.bf16.f32 "
        "{%0,%1,%2,%3}, {%4,%5,%6,%7}, {%8,%9}, {%0,%1,%2,%3};"
        : "+f"(c[0]), "+f"(c[1]), "+f"(c[2]), "+f"(c[3])
        : "r"(a[0]), "r"(a[1]), "r"(a[2]), "r"(a[3]), "r"(b0), "r"(b1));
}

// ---------------- kernel 1: bf16 convert + exact fp32 row norms ----------------
__global__ void prep_kernel(const float* __restrict__ x) {
    int warp = (blockIdx.x * blockDim.x + threadIdx.x) >> 5;
    int lane = threadIdx.x & 31;
    if (warp >= N_DIM) return;
    const float* row = x + (size_t)warp * D_DIM;
    __nv_bfloat16* dst = g_xb + (size_t)warp * D_DIM;
    float s = 0.f;
    #pragma unroll
    for (int c = lane; c < D_DIM; c += 32) {
        float v = row[c];
        s += v * v;
        dst[c] = __float2bfloat16(v);
    }
    #pragma unroll
    for (int o = 16; o; o >>= 1) s += __shfl_xor_sync(0xffffffffu, s, o);
    if (lane == 0) g_sq[warp] = s;
}

// ---------------- kernel 2: mma.sync GEMM + d2 epilogue + partial sum ----------
// SMEM: A tile 128x256 bf16, row stride 528 B (512 data + 16 pad -> ldmatrix
// conflict-free: row stride mod 128 = 16). B tile identical. Total 132 KB.
#define ROW_BYTES 528
#define A_TILE_BYTES (TILE * ROW_BYTES)        // 67584
#define GEMM_SMEM (2 * A_TILE_BYTES)           // 135168

__global__ __launch_bounds__(256, 1)
void gemm_d2_kernel(float* __restrict__ d_out) {
    extern __shared__ char smem[];
    char* As = smem;
    char* Bs = smem + A_TILE_BYTES;
    const uint32_t As_u = smem_to_u32(As);
    const uint32_t Bs_u = smem_to_u32(Bs);

    const int tid  = threadIdx.x;
    const int wid  = tid >> 5;
    const int lane = tid & 31;

    const int tile_i = blockIdx.x / GRID_TILES;
    const int tile_j = blockIdx.x % GRID_TILES;
    const int row0 = tile_i * TILE;
    const int col0 = tile_j * TILE;

    // ---- load tiles (16B chunks) ----
    {
        const uint4* srcA = reinterpret_cast<const uint4*>(g_xb) + (size_t)row0 * 32;
        const uint4* srcB = reinterpret_cast<const uint4*>(g_xb) + (size_t)col0 * 32;
        #pragma unroll
        for (int it = 0; it < 16; it++) {
            int idx = tid + it * 256;
            int r = idx >> 5, c = idx & 31;
            uint32_t off = (uint32_t)r * ROW_BYTES + (uint32_t)c * 16;
            *reinterpret_cast<uint4*>(As + off) = srcA[idx];
            *reinterpret_cast<uint4*>(Bs + off) = srcB[idx];
        }
    }
    __syncthreads();

    // ---- warp tiling: 4 warps along M (32 rows each), 2 along N (64 cols each)
    const int warp_m = wid & 3;
    const int warp_n = wid >> 2;
    const int m0 = warp_m * 32;
    const int n0 = warp_n * 64;

    float acc[2][8][4];
    #pragma unroll
    for (int mi = 0; mi < 2; mi++)
        #pragma unroll
        for (int ni = 0; ni < 8; ni++)
            #pragma unroll
            for (int q = 0; q < 4; q++) acc[mi][ni][q] = 0.f;

    // Precompute lane-dependent ldmatrix address components.
    // A x4: lanes 0-15 -> rows m0..m15 (k-lo), lanes 16-31 -> same rows (k-hi)
    const uint32_t a_row = (uint32_t)(lane & 15);
    const uint32_t a_kof = (uint32_t)((lane >> 4) << 3);
    // B x4: group g = lane>>3; rows: n + (g>=2 ? 8 : 0) + (lane&7); k-off: (g&1)*8
    const uint32_t b_row = (uint32_t)(((lane >> 4) << 3) + (lane & 7));
    const uint32_t b_kof = (uint32_t)(((lane >> 3) & 1) << 3);

    #pragma unroll
    for (int ks = 0; ks < 16; ks++) {
        const uint32_t kbase = (uint32_t)ks * 32;  // 16 bf16 = 32 bytes
        uint32_t aa[2][4];
        #pragma unroll
        for (int mi = 0; mi < 2; mi++) {
            uint32_t addr = As_u + (m0 + mi * 16 + a_row) * ROW_BYTES
                          + kbase + a_kof * 2;
            ldsm_x4(aa[mi], addr);
        }
        uint32_t bb[4][4];
        #pragma unroll
        for (int nb = 0; nb < 4; nb++) {
            uint32_t addr = Bs_u + (n0 + nb * 16 + b_row) * ROW_BYTES
                          + kbase + b_kof * 2;
            ldsm_x4(bb[nb], addr);
        }
        #pragma unroll
        for (int mi = 0; mi < 2; mi++)
            #pragma unroll
            for (int ni = 0; ni < 8; ni++) {
                int nb = ni >> 1, hi = ni & 1;
                mma_16816_bf16(acc[mi][ni], aa[mi], bb[nb][hi * 2], bb[nb][hi * 2 + 1]);
            }
    }

    // ---- epilogue: d2 = sqi + sqj - 2*gram, clamp, store, partial-sum ----
    float lsum = 0.f;
    #pragma unroll
    for (int mi = 0; mi < 2; mi++) {
        const int gi = row0 + m0 + mi * 16 + (lane >> 2);
        const float sqi0 = g_sq[gi];
        const float sqi8 = g_sq[gi + 8];
        #pragma unroll
        for (int ni = 0; ni < 8; ni++) {
            const int gj = col0 + n0 + ni * 8 + ((lane & 3) << 1);
            const float2 sj = *reinterpret_cast<const float2*>(&g_sq[gj]);
            float d0 = fmaxf(sqi0 + sj.x - 2.f * acc[mi][ni][0], 0.f);
            float d1 = fmaxf(sqi0 + sj.y - 2.f * acc[mi][ni][1], 0.f);
            float d2 = fmaxf(sqi8 + sj.x - 2.f * acc[mi][ni][2], 0.f);
            float d3 = fmaxf(sqi8 + sj.y - 2.f * acc[mi][ni][3], 0.f);
            lsum += (d0 + d1) + (d2 + d3);
            *reinterpret_cast<float2*>(&d_out[(size_t)gi * N_DIM + gj])       = make_float2(d0, d1);
            *reinterpret_cast<float2*>(&d_out[(size_t)(gi + 8) * N_DIM + gj]) = make_float2(d2, d3);
        }
    }

    // deterministic per-CTA reduction
    #pragma unroll
    for (int o = 16; o; o >>= 1) lsum += __shfl_xor_sync(0xffffffffu, lsum, o);
    __shared__ float wsum[8];
    if (lane == 0) wsum[wid] = lsum;
    __syncthreads();
    if (tid == 0) {
        float s = 0.f;
        #pragma unroll
        for (int w = 0; w < 8; w++) s += wsum[w];
        g_partial[blockIdx.x] = s;
    }
}

// ---------------- kernel 3: fold partials -> 1/(2*sigma^2) ----------------
__global__ void reduce_kernel() {
    int tid = threadIdx.x;
    double v = (double)g_partial[tid];  // 1024 threads, 1024 partials
    #pragma unroll
    for (int o = 16; o; o >>= 1) v += __shfl_xor_sync(0xffffffffu, v, o);
    __shared__ double sh[32];
    if ((tid & 31) == 0) sh[tid >> 5] = v;
    __syncthreads();
    if (tid < 32) {
        double t = sh[tid];
        #pragma unroll
        for (int o = 16; o; o >>= 1) t += __shfl_xor_sync(0xffffffffu, t, o);
        if (tid == 0) {
            double mean = t / ((double)N_DIM * (double)N_DIM);
            g_inv = (float)(1.0 / (2.0 * mean));   // ALPHA = 1
        }
    }
}

// ---------------- kernel 4: in-place exp ----------------
__global__ void exp_kernel(float* __restrict__ d_out) {
    const float inv = g_inv;
    float4* p = reinterpret_cast<float4*>(d_out);
    const size_t total4 = (size_t)N_DIM * N_DIM / 4;
    size_t i = (size_t)blockIdx.x * blockDim.x + threadIdx.x;
    const size_t stride = (size_t)gridDim.x * blockDim.x;
    for (; i < total4; i += stride) {
        float4 v = p[i];
        v.x = __expf(-v.x * inv);
        v.y = __expf(-v.y * inv);
        v.z = __expf(-v.z * inv);
        v.w = __expf(-v.w * inv);
        p[i] = v;
    }
}

// ---------------- launcher ----------------
extern "C" void kernel_launch(void* const* d_in, const int* in_sizes, int n_in,
                              void* d_out, int out_size) {
    const float* x = (const float*)d_in[0];
    float* out = (float*)d_out;

    static bool attr_set = false;
    if (!attr_set) {
        cudaFuncSetAttribute(gemm_d2_kernel,
                             cudaFuncAttributeMaxDynamicSharedMemorySize, GEMM_SMEM);
        attr_set = true;
    }

    prep_kernel<<<512, 256>>>(x);
    gemm_d2_kernel<<<NUM_CTAS, 256, GEMM_SMEM>>>(out);
    reduce_kernel<<<1, 1024>>>();
    exp_kernel<<<4096, 256>>>(out);
}

// round 4
// speedup vs baseline: 1.1908x; 1.1908x over previous
#include <cuda_runtime.h>
#include <cuda_bf16.h>
#include <cstdint>

#define N_DIM 4096
#define D_DIM 256
#define TILE  128
#define GRID_TILES (N_DIM / TILE)                     // 32
#define NUM_UTILES (GRID_TILES * (GRID_TILES + 1) / 2) // 528

// ---------------- device scratch (no allocation allowed) ----------------
__device__ __nv_bfloat16 g_xb[N_DIM * D_DIM];     // 2 MB bf16 copy of x
__device__ float g_sq[N_DIM];                      // row squared norms (fp32 exact)
__device__ float g_svec_partial[32][D_DIM];        // per-block column-sum partials
__device__ float g_inv;                            // 1 / (2 * sigma^2)

// ---------------- helpers ----------------
__device__ __forceinline__ uint32_t smem_to_u32(const void* p) {
    uint32_t a;
    asm("{ .reg .u64 t; cvta.to.shared.u64 t, %1; cvt.u32.u64 %0, t; }" : "=r"(a) : "l"(p));
    return a;
}

__device__ __forceinline__ void ldsm_x4(uint32_t r[4], uint32_t addr) {
    asm volatile("ldmatrix.sync.aligned.m8n8.x4.shared.b16 {%0,%1,%2,%3}, [%4];"
                 : "=r"(r[0]), "=r"(r[1]), "=r"(r[2]), "=r"(r[3]) : "r"(addr));
}

__device__ __forceinline__ void mma_16816_bf16(float c[4], const uint32_t a[4],
                                               uint32_t b0, uint32_t b1) {
    asm volatile(
        "mma.sync.aligned.m16n8k16.row.col.f32.bf16.bf16.f32 "
        "{%0,%1,%2,%3}, {%4,%5,%6,%7}, {%8,%9}, {%0,%1,%2,%3};"
        : "+f"(c[0]), "+f"(c[1]), "+f"(c[2]), "+f"(c[3])
        : "r"(a[0]), "r"(a[1]), "r"(a[2]), "r"(a[3]), "r"(b0), "r"(b1));
}

// ---------------- kernel 1: bf16 convert + exact fp32 row norms ----------------
__global__ void prep_kernel(const float* __restrict__ x) {
    int warp = (blockIdx.x * blockDim.x + threadIdx.x) >> 5;
    int lane = threadIdx.x & 31;
    if (warp >= N_DIM) return;
    const float* row = x + (size_t)warp * D_DIM;
    __nv_bfloat16* dst = g_xb + (size_t)warp * D_DIM;
    float s = 0.f;
    #pragma unroll
    for (int c = lane; c < D_DIM; c += 32) {
        float v = row[c];
        s += v * v;
        dst[c] = __float2bfloat16(v);
    }
    #pragma unroll
    for (int o = 16; o; o >>= 1) s += __shfl_xor_sync(0xffffffffu, s, o);
    if (lane == 0) g_sq[warp] = s;
}

// ---------------- kernel 1b: deterministic column-sum partials ----------------
__global__ void colsum_kernel(const float* __restrict__ x) {
    const int b = blockIdx.x;     // 32 blocks, 128 rows each
    const int t = threadIdx.x;    // 256 threads = one column each
    const float* base = x + (size_t)b * 128 * D_DIM + t;
    float acc = 0.f;
    #pragma unroll 8
    for (int r = 0; r < 128; r++) acc += base[(size_t)r * D_DIM];
    g_svec_partial[b][t] = acc;
}

// ---------------- kernel 1c: sigma -> g_inv (single block, deterministic) -----
__global__ void sigma_kernel() {
    const int t = threadIdx.x;   // 256 threads
    // column sums -> ||s||^2 contribution
    double sc = 0.0;
    #pragma unroll
    for (int b = 0; b < 32; b++) sc += (double)g_svec_partial[b][t];
    double ss = sc * sc;
    // sum of row norms (4096 values, 16 per thread, fixed order)
    double sq = 0.0;
    #pragma unroll
    for (int k = 0; k < 16; k++) sq += (double)g_sq[t + k * 256];

    // block reduction in shared (deterministic tree)
    __shared__ double sh_ss[256], sh_sq[256];
    sh_ss[t] = ss; sh_sq[t] = sq;
    __syncthreads();
    for (int o = 128; o; o >>= 1) {
        if (t < o) { sh_ss[t] += sh_ss[t + o]; sh_sq[t] += sh_sq[t + o]; }
        __syncthreads();
    }
    if (t == 0) {
        const double N = (double)N_DIM;
        double mean_d2 = 2.0 * sh_sq[0] / N - 2.0 * sh_ss[0] / (N * N);
        g_inv = (float)(1.0 / (2.0 * mean_d2));  // ALPHA = 1
    }
}

// ---------------- kernel 2: fused symmetric GEMM + d2 + exp ----------
// SMEM: A tile 128x256 bf16, row stride 528 B (512 data + 16 pad -> ldmatrix
// conflict-free). B tile identical. 132 KB. A-region reused as fp32 transpose
// staging buffer (128 x 129 floats = 64.5 KB) for the mirror-tile store.
#define ROW_BYTES 528
#define A_TILE_BYTES (TILE * ROW_BYTES)        // 67584
#define GEMM_SMEM (2 * A_TILE_BYTES)           // 135168
#define T_ST 129                               // transpose buffer row stride (floats)

__global__ __launch_bounds__(256, 1)
void gemm_fused_kernel(float* __restrict__ d_out) {
    extern __shared__ char smem[];
    char* As = smem;
    char* Bs = smem + A_TILE_BYTES;
    const uint32_t As_u = smem_to_u32(As);
    const uint32_t Bs_u = smem_to_u32(Bs);

    const int tid  = threadIdx.x;
    const int wid  = tid >> 5;
    const int lane = tid & 31;

    // decode upper-triangular tile index: row ti has (32 - ti) tiles
    int b = blockIdx.x, ti = 0, rem = GRID_TILES;
    while (b >= rem) { b -= rem; rem--; ti++; }
    const int tj = ti + b;
    const bool diag = (ti == tj);
    const int row0 = ti * TILE;
    const int col0 = tj * TILE;

    // ---- load tiles (16B chunks) ----
    {
        const uint4* srcA = reinterpret_cast<const uint4*>(g_xb) + (size_t)row0 * 32;
        const uint4* srcB = reinterpret_cast<const uint4*>(g_xb) + (size_t)col0 * 32;
        #pragma unroll
        for (int it = 0; it < 16; it++) {
            int idx = tid + it * 256;
            int r = idx >> 5, c = idx & 31;
            uint32_t off = (uint32_t)r * ROW_BYTES + (uint32_t)c * 16;
            *reinterpret_cast<uint4*>(As + off) = srcA[idx];
            *reinterpret_cast<uint4*>(Bs + off) = srcB[idx];
        }
    }
    __syncthreads();

    // ---- warp tiling: 4 warps along M (32 rows), 2 along N (64 cols) ----
    const int warp_m = wid & 3;
    const int warp_n = wid >> 2;
    const int m0 = warp_m * 32;
    const int n0 = warp_n * 64;

    float acc[2][8][4];
    #pragma unroll
    for (int mi = 0; mi < 2; mi++)
        #pragma unroll
        for (int ni = 0; ni < 8; ni++)
            #pragma unroll
            for (int q = 0; q < 4; q++) acc[mi][ni][q] = 0.f;

    const uint32_t a_row = (uint32_t)(lane & 15);
    const uint32_t a_kof = (uint32_t)((lane >> 4) << 3);
    const uint32_t b_row = (uint32_t)(((lane >> 4) << 3) + (lane & 7));
    const uint32_t b_kof = (uint32_t)(((lane >> 3) & 1) << 3);

    #pragma unroll
    for (int ks = 0; ks < 16; ks++) {
        const uint32_t kbase = (uint32_t)ks * 32;
        uint32_t aa[2][4];
        #pragma unroll
        for (int mi = 0; mi < 2; mi++) {
            uint32_t addr = As_u + (m0 + mi * 16 + a_row) * ROW_BYTES + kbase + a_kof * 2;
            ldsm_x4(aa[mi], addr);
        }
        uint32_t bb[4][4];
        #pragma unroll
        for (int nb = 0; nb < 4; nb++) {
            uint32_t addr = Bs_u + (n0 + nb * 16 + b_row) * ROW_BYTES + kbase + b_kof * 2;
            ldsm_x4(bb[nb], addr);
        }
        #pragma unroll
        for (int mi = 0; mi < 2; mi++)
            #pragma unroll
            for (int ni = 0; ni < 8; ni++) {
                int nb = ni >> 1, hi = ni & 1;
                mma_16816_bf16(acc[mi][ni], aa[mi], bb[nb][hi * 2], bb[nb][hi * 2 + 1]);
            }
    }

    __syncthreads();  // all warps done reading As before it is reused as transpose buf

    // ---- fused epilogue: d2 = sqi + sqj - 2*gram, clamp, exp, store ----
    const float inv = g_inv;
    float* trans = reinterpret_cast<float*>(As);

    #pragma unroll
    for (int mi = 0; mi < 2; mi++) {
        const int rl0 = m0 + mi * 16 + (lane >> 2);   // local row (0..127)
        const int gi  = row0 + rl0;
        const float sqi0 = g_sq[gi];
        const float sqi8 = g_sq[gi + 8];
        #pragma unroll
        for (int ni = 0; ni < 8; ni++) {
            const int cl = n0 + ni * 8 + ((lane & 3) << 1);  // local col (0..127)
            const int gj = col0 + cl;
            const float2 sj = *reinterpret_cast<const float2*>(&g_sq[gj]);
            float e0 = __expf(-fmaxf(sqi0 + sj.x - 2.f * acc[mi][ni][0], 0.f) * inv);
            float e1 = __expf(-fmaxf(sqi0 + sj.y - 2.f * acc[mi][ni][1], 0.f) * inv);
            float e2 = __expf(-fmaxf(sqi8 + sj.x - 2.f * acc[mi][ni][2], 0.f) * inv);
            float e3 = __expf(-fmaxf(sqi8 + sj.y - 2.f * acc[mi][ni][3], 0.f) * inv);
            *reinterpret_cast<float2*>(&d_out[(size_t)gi * N_DIM + gj])       = make_float2(e0, e1);
            *reinterpret_cast<float2*>(&d_out[(size_t)(gi + 8) * N_DIM + gj]) = make_float2(e2, e3);
            if (!diag) {
                trans[(cl)     * T_ST + rl0]     = e0;
                trans[(cl + 1) * T_ST + rl0]     = e1;
                trans[(cl)     * T_ST + rl0 + 8] = e2;
                trans[(cl + 1) * T_ST + rl0 + 8] = e3;
            }
        }
    }

    if (!diag) {
        __syncthreads();
        // coalesced mirror store: tile [col0..col0+127] x [row0..row0+127]
        #pragma unroll
        for (int it = 0; it < 16; it++) {
            int e4 = tid + it * 256;       // 4096 float4s
            int r  = e4 >> 5;              // 0..127 (global row = col0 + r)
            int c4 = e4 & 31;              // float4 index within row
            const float* src = &trans[r * T_ST + c4 * 4];
            float4 v = make_float4(src[0], src[1], src[2], src[3]);
            *reinterpret_cast<float4*>(&d_out[(size_t)(col0 + r) * N_DIM + row0 + c4 * 4]) = v;
        }
    }
}

// ---------------- launcher ----------------
extern "C" void kernel_launch(void* const* d_in, const int* in_sizes, int n_in,
                              void* d_out, int out_size) {
    const float* x = (const float*)d_in[0];
    float* out = (float*)d_out;

    static bool attr_set = false;
    if (!attr_set) {
        cudaFuncSetAttribute(gemm_fused_kernel,
                             cudaFuncAttributeMaxDynamicSharedMemorySize, GEMM_SMEM);
        attr_set = true;
    }

    prep_kernel<<<512, 256>>>(x);
    colsum_kernel<<<32, 256>>>(x);
    sigma_kernel<<<1, 256>>>();
    gemm_fused_kernel<<<NUM_UTILES, 256, GEMM_SMEM>>>(out);
}

// round 5
// speedup vs baseline: 1.3645x; 1.1458x over previous
#include <cuda_runtime.h>
#include <cuda_bf16.h>
#include <cstdint>

#define N_DIM 4096
#define D_DIM 256
#define TILE  128
#define GRID_TILES (N_DIM / TILE)                      // 32
#define NUM_UTILES (GRID_TILES * (GRID_TILES + 1) / 2) // 528

// ---------------- device scratch (no allocation allowed) ----------------
__device__ __nv_bfloat16 g_xb[N_DIM * D_DIM];     // 2 MB bf16 copy of x
__device__ float g_sq[N_DIM];                      // row squared norms (fp32 exact)
__device__ float g_svec_partial[512][D_DIM];       // per-block colsum partials
__device__ float g_inv;                            // 1 / (2 * sigma^2)

// ---------------- helpers ----------------
__device__ __forceinline__ uint32_t smem_to_u32(const void* p) {
    uint32_t a;
    asm("{ .reg .u64 t; cvta.to.shared.u64 t, %1; cvt.u32.u64 %0, t; }" : "=r"(a) : "l"(p));
    return a;
}

__device__ __forceinline__ void ldsm_x4(uint32_t r[4], uint32_t addr) {
    asm volatile("ldmatrix.sync.aligned.m8n8.x4.shared.b16 {%0,%1,%2,%3}, [%4];"
                 : "=r"(r[0]), "=r"(r[1]), "=r"(r[2]), "=r"(r[3]) : "r"(addr));
}

__device__ __forceinline__ void mma_16816_bf16(float c[4], const uint32_t a[4],
                                               uint32_t b0, uint32_t b1) {
    asm volatile(
        "mma.sync.aligned.m16n8k16.row.col.f32.bf16.bf16.f32 "
        "{%0,%1,%2,%3}, {%4,%5,%6,%7}, {%8,%9}, {%0,%1,%2,%3};"
        : "+f"(c[0]), "+f"(c[1]), "+f"(c[2]), "+f"(c[3])
        : "r"(a[0]), "r"(a[1]), "r"(a[2]), "r"(a[3]), "r"(b0), "r"(b1));
}

#define CP_ASYNC_16(dst, src) \
    asm volatile("cp.async.cg.shared.global [%0], [%1], 16;" :: "r"(dst), "l"(src))
#define CP_ASYNC_COMMIT() asm volatile("cp.async.commit_group;" ::: "memory")
#define CP_ASYNC_WAIT(n)  asm volatile("cp.async.wait_group %0;" :: "n"(n) : "memory")

// ---------------- kernel 1: bf16 convert + row norms + colsum partials --------
__global__ void prep_kernel(const float* __restrict__ x) {
    const int tid  = threadIdx.x;
    const int wrow = blockIdx.x * 8 + (tid >> 5);   // warp per row, 8 rows/block
    const int lane = tid & 31;
    {
        const float* row = x + (size_t)wrow * D_DIM;
        __nv_bfloat16* dst = g_xb + (size_t)wrow * D_DIM;
        float s = 0.f;
        #pragma unroll
        for (int c = lane; c < D_DIM; c += 32) {
            float v = row[c];
            s += v * v;
            dst[c] = __float2bfloat16(v);
        }
        #pragma unroll
        for (int o = 16; o; o >>= 1) s += __shfl_xor_sync(0xffffffffu, s, o);
        if (lane == 0) g_sq[wrow] = s;
    }
    // colsum partial over this block's 8 rows (thread t = column t, coalesced)
    const float* base = x + (size_t)blockIdx.x * 8 * D_DIM + tid;
    float acc = 0.f;
    #pragma unroll
    for (int r = 0; r < 8; r++) acc += base[r * D_DIM];
    g_svec_partial[blockIdx.x][tid] = acc;
}

// ---------------- kernel 2: sigma -> g_inv (single block, deterministic) ------
__global__ void sigma_kernel() {
    const int t = threadIdx.x;   // 256 threads
    double sc = 0.0;
    for (int b = 0; b < 512; b++) sc += (double)g_svec_partial[b][t];
    double ss = sc * sc;
    double sq = 0.0;
    #pragma unroll
    for (int k = 0; k < 16; k++) sq += (double)g_sq[t + k * 256];

    __shared__ double sh_ss[256], sh_sq[256];
    sh_ss[t] = ss; sh_sq[t] = sq;
    __syncthreads();
    for (int o = 128; o; o >>= 1) {
        if (t < o) { sh_ss[t] += sh_ss[t + o]; sh_sq[t] += sh_sq[t + o]; }
        __syncthreads();
    }
    if (t == 0) {
        const double N = (double)N_DIM;
        double mean_d2 = 2.0 * sh_sq[0] / N - 2.0 * sh_ss[0] / (N * N);
        g_inv = (float)(1.0 / (2.0 * mean_d2));  // ALPHA = 1
    }
}

// ---------------- kernel 3: fused symmetric GEMM + d2 + exp (pipelined) -------
// K split into 4 chunks of 64. Stage: A 128x64 bf16 (144 B/row, pad for
// conflict-free ldmatrix) + B same = 36864 B. Two stages = 73728 B, also reused
// as the fp32 transpose staging buffer (128 x 132 floats = 67584 B).
#define CHUNK_K    64
#define NCHUNK     (D_DIM / CHUNK_K)     // 4
#define CROW_BYTES 144
#define STAGE_A_BYTES (TILE * CROW_BYTES)         // 18432
#define STAGE_BYTES   (2 * STAGE_A_BYTES)         // 36864
#define GEMM_SMEM     (2 * STAGE_BYTES)           // 73728
#define T_ST 132

__global__ __launch_bounds__(256, 2)
void gemm_fused_kernel(float* __restrict__ d_out) {
    extern __shared__ char smem[];
    const uint32_t smem_u = smem_to_u32(smem);

    const int tid  = threadIdx.x;
    const int wid  = tid >> 5;
    const int lane = tid & 31;

    // decode upper-triangular tile index
    int b = blockIdx.x, ti = 0, rem = GRID_TILES;
    while (b >= rem) { b -= rem; rem--; ti++; }
    const int tj = ti + b;
    const bool diag = (ti == tj);
    const int row0 = ti * TILE;
    const int col0 = tj * TILE;

    // per-thread cp.async source/dest components (4 chunks of 16B per tile)
    // idx = tid + it*256; r = idx>>3, q = idx&7
    const __nv_bfloat16* gA = g_xb + (size_t)row0 * D_DIM;
    const __nv_bfloat16* gB = g_xb + (size_t)col0 * D_DIM;

    auto load_chunk = [&](int c, int stage) {
        const uint32_t sA = smem_u + stage * STAGE_BYTES;
        const uint32_t sB = sA + STAGE_A_BYTES;
        #pragma unroll
        for (int it = 0; it < 4; it++) {
            int idx = tid + it * 256;
            int r = idx >> 3, q = idx & 7;
            uint32_t soff = (uint32_t)r * CROW_BYTES + (uint32_t)q * 16;
            size_t goff = (size_t)r * D_DIM + c * CHUNK_K + q * 8;
            CP_ASYNC_16(sA + soff, gA + goff);
            CP_ASYNC_16(sB + soff, gB + goff);
        }
        CP_ASYNC_COMMIT();
    };

    // warp tiling: 4 warps along M (32 rows), 2 along N (64 cols)
    const int warp_m = wid & 3;
    const int warp_n = wid >> 2;
    const int m0 = warp_m * 32;
    const int n0 = warp_n * 64;

    float acc[2][8][4];
    #pragma unroll
    for (int mi = 0; mi < 2; mi++)
        #pragma unroll
        for (int ni = 0; ni < 8; ni++)
            #pragma unroll
            for (int q = 0; q < 4; q++) acc[mi][ni][q] = 0.f;

    const uint32_t a_row = (uint32_t)(lane & 15);
    const uint32_t a_kof = (uint32_t)((lane >> 4) << 3);
    const uint32_t b_row = (uint32_t)(((lane >> 4) << 3) + (lane & 7));
    const uint32_t b_kof = (uint32_t)(((lane >> 3) & 1) << 3);

    load_chunk(0, 0);

    #pragma unroll
    for (int c = 0; c < NCHUNK; c++) {
        const int stage = c & 1;
        if (c + 1 < NCHUNK) load_chunk(c + 1, (c + 1) & 1);
        if (c + 1 < NCHUNK) { CP_ASYNC_WAIT(1); } else { CP_ASYNC_WAIT(0); }
        __syncthreads();

        const uint32_t As_u = smem_u + stage * STAGE_BYTES;
        const uint32_t Bs_u = As_u + STAGE_A_BYTES;

        #pragma unroll
        for (int ks = 0; ks < CHUNK_K / 16; ks++) {
            const uint32_t kbase = (uint32_t)ks * 32;
            uint32_t aa[2][4];
            #pragma unroll
            for (int mi = 0; mi < 2; mi++) {
                uint32_t addr = As_u + (m0 + mi * 16 + a_row) * CROW_BYTES + kbase + a_kof * 2;
                ldsm_x4(aa[mi], addr);
            }
            uint32_t bb[4][4];
            #pragma unroll
            for (int nb = 0; nb < 4; nb++) {
                uint32_t addr = Bs_u + (n0 + nb * 16 + b_row) * CROW_BYTES + kbase + b_kof * 2;
                ldsm_x4(bb[nb], addr);
            }
            #pragma unroll
            for (int mi = 0; mi < 2; mi++)
                #pragma unroll
                for (int ni = 0; ni < 8; ni++) {
                    int nb = ni >> 1, hi = ni & 1;
                    mma_16816_bf16(acc[mi][ni], aa[mi], bb[nb][hi * 2], bb[nb][hi * 2 + 1]);
                }
        }
        __syncthreads();   // stage consumed; next iteration may overwrite it
    }

    // ---- fused epilogue: d2 = sqi + sqj - 2*gram, clamp, exp, store ----
    const float inv = g_inv;
    float* trans = reinterpret_cast<float*>(smem);

    #pragma unroll
    for (int mi = 0; mi < 2; mi++) {
        const int rl0 = m0 + mi * 16 + (lane >> 2);   // local row (0..127)
        const int gi  = row0 + rl0;
        const float sqi0 = g_sq[gi];
        const float sqi8 = g_sq[gi + 8];
        #pragma unroll
        for (int ni = 0; ni < 8; ni++) {
            const int cl = n0 + ni * 8 + ((lane & 3) << 1);  // local col (0..127)
            const int gj = col0 + cl;
            const float2 sj = *reinterpret_cast<const float2*>(&g_sq[gj]);
            float e0 = __expf(-fmaxf(sqi0 + sj.x - 2.f * acc[mi][ni][0], 0.f) * inv);
            float e1 = __expf(-fmaxf(sqi0 + sj.y - 2.f * acc[mi][ni][1], 0.f) * inv);
            float e2 = __expf(-fmaxf(sqi8 + sj.x - 2.f * acc[mi][ni][2], 0.f) * inv);
            float e3 = __expf(-fmaxf(sqi8 + sj.y - 2.f * acc[mi][ni][3], 0.f) * inv);
            *reinterpret_cast<float2*>(&d_out[(size_t)gi * N_DIM + gj])       = make_float2(e0, e1);
            *reinterpret_cast<float2*>(&d_out[(size_t)(gi + 8) * N_DIM + gj]) = make_float2(e2, e3);
            if (!diag) {
                trans[(cl)     * T_ST + rl0]     = e0;
                trans[(cl + 1) * T_ST + rl0]     = e1;
                trans[(cl)     * T_ST + rl0 + 8] = e2;
                trans[(cl + 1) * T_ST + rl0 + 8] = e3;
            }
        }
    }

    if (!diag) {
        __syncthreads();
        // coalesced mirror store: tile [col0..col0+127] x [row0..row0+127]
        #pragma unroll
        for (int it = 0; it < 16; it++) {
            int e4 = tid + it * 256;       // 4096 float4s
            int r  = e4 >> 5;              // global row = col0 + r
            int c4 = e4 & 31;
            const float* src = &trans[r * T_ST + c4 * 4];
            float4 v = make_float4(src[0], src[1], src[2], src[3]);
            *reinterpret_cast<float4*>(&d_out[(size_t)(col0 + r) * N_DIM + row0 + c4 * 4]) = v;
        }
    }
}

// ---------------- launcher ----------------
extern "C" void kernel_launch(void* const* d_in, const int* in_sizes, int n_in,
                              void* d_out, int out_size) {
    const float* x = (const float*)d_in[0];
    float* out = (float*)d_out;

    static bool attr_set = false;
    if (!attr_set) {
        cudaFuncSetAttribute(gemm_fused_kernel,
                             cudaFuncAttributeMaxDynamicSharedMemorySize, GEMM_SMEM);
        attr_set = true;
    }

    prep_kernel<<<512, 256>>>(x);
    sigma_kernel<<<1, 256>>>();
    gemm_fused_kernel<<<NUM_UTILES, 256, GEMM_SMEM>>>(out);
}

// round 7
// speedup vs baseline: 1.3920x; 1.0202x over previous
#include <cuda_runtime.h>
#include <cuda_bf16.h>
#include <cstdint>

#define N_DIM 4096
#define D_DIM 256
#define TILE  128
#define GRID_TILES (N_DIM / TILE)                      // 32
#define NUM_UTILES (GRID_TILES * (GRID_TILES + 1) / 2) // 528

// ---------------- device scratch (no allocation allowed) ----------------
__device__ __nv_bfloat16 g_xb[N_DIM * D_DIM];     // 2 MB bf16 copy of x
__device__ float g_sq[N_DIM];                      // row squared norms (fp32 exact)
__device__ float g_svec_partial[512][D_DIM];       // per-block colsum partials
__device__ float g_inv;                            // 1 / (2 * sigma^2)

// ---------------- helpers ----------------
__device__ __forceinline__ uint32_t smem_to_u32(const void* p) {
    uint32_t a;
    asm("{ .reg .u64 t; cvta.to.shared.u64 t, %1; cvt.u32.u64 %0, t; }" : "=r"(a) : "l"(p));
    return a;
}

__device__ __forceinline__ void ldsm_x4(uint32_t r[4], uint32_t addr) {
    asm volatile("ldmatrix.sync.aligned.m8n8.x4.shared.b16 {%0,%1,%2,%3}, [%4];"
                 : "=r"(r[0]), "=r"(r[1]), "=r"(r[2]), "=r"(r[3]) : "r"(addr));
}

__device__ __forceinline__ void mma_16816_bf16(float c[4], const uint32_t a[4],
                                               uint32_t b0, uint32_t b1) {
    asm volatile(
        "mma.sync.aligned.m16n8k16.row.col.f32.bf16.bf16.f32 "
        "{%0,%1,%2,%3}, {%4,%5,%6,%7}, {%8,%9}, {%0,%1,%2,%3};"
        : "+f"(c[0]), "+f"(c[1]), "+f"(c[2]), "+f"(c[3])
        : "r"(a[0]), "r"(a[1]), "r"(a[2]), "r"(a[3]), "r"(b0), "r"(b1));
}

#define CP_ASYNC_16(dst, src) \
    asm volatile("cp.async.cg.shared.global [%0], [%1], 16;" :: "r"(dst), "l"(src))
#define CP_ASYNC_COMMIT() asm volatile("cp.async.commit_group;" ::: "memory")
#define CP_ASYNC_WAIT(n)  asm volatile("cp.async.wait_group %0;" :: "n"(n) : "memory")

// ---------------- kernel 1: bf16 convert + row norms + colsum partials --------
__global__ void prep_kernel(const float* __restrict__ x) {
    const int tid  = threadIdx.x;
    const int wid  = tid >> 5;
    const int lane = tid & 31;
    const int wrow = blockIdx.x * 8 + wid;   // warp per row

    {
        const float4* row = reinterpret_cast<const float4*>(x + (size_t)wrow * D_DIM);
        uint2* dst = reinterpret_cast<uint2*>(g_xb + (size_t)wrow * D_DIM);
        float s = 0.f;
        #pragma unroll
        for (int i = 0; i < 2; i++) {
            float4 v = row[lane + i * 32];
            s += v.x * v.x + v.y * v.y + v.z * v.z + v.w * v.w;
            __nv_bfloat162 lo = __float22bfloat162_rn(make_float2(v.x, v.y));
            __nv_bfloat162 hi = __float22bfloat162_rn(make_float2(v.z, v.w));
            dst[lane + i * 32] = make_uint2(*reinterpret_cast<uint32_t*>(&lo),
                                            *reinterpret_cast<uint32_t*>(&hi));
        }
        #pragma unroll
        for (int o = 16; o; o >>= 1) s += __shfl_xor_sync(0xffffffffu, s, o);
        if (lane == 0) g_sq[wrow] = s;
    }
    // colsum partial over this block's 8 rows (thread t = column t, coalesced)
    const float* base = x + (size_t)blockIdx.x * 8 * D_DIM + tid;
    float acc = 0.f;
    #pragma unroll
    for (int r = 0; r < 8; r++) acc += base[r * D_DIM];
    g_svec_partial[blockIdx.x][tid] = acc;
}

// ---------------- kernel 2: sigma -> g_inv (single block, deterministic) ------
__global__ void sigma_kernel() {
    const int t   = threadIdx.x;      // 1024 threads
    const int col = t & 255;
    const int grp = t >> 8;           // 4 groups of 128 partial-rows each

    float scp = 0.f;
    #pragma unroll 8
    for (int b = grp * 128; b < grp * 128 + 128; b++) scp += g_svec_partial[b][col];

    __shared__ float sh_sc[4][256];
    sh_sc[grp][col] = scp;

    // row-norm sum: 4096 values, 4 per thread, fixed order
    double sq = 0.0;
    #pragma unroll
    for (int k = 0; k < 4; k++) sq += (double)g_sq[t + k * 1024];

    __shared__ double sh[1024];
    sh[t] = sq;
    __syncthreads();

    // ss = sum over cols of (total colsum)^2
    double ss = 0.0;
    if (t < 256) {
        double sc = (double)sh_sc[0][t] + (double)sh_sc[1][t]
                  + (double)sh_sc[2][t] + (double)sh_sc[3][t];
        ss = sc * sc;
    }
    __shared__ double sh_ss[256];
    if (t < 256) sh_ss[t] = ss;
    __syncthreads();

    // tree-reduce sq (1024) and ss (256)
    for (int o = 512; o; o >>= 1) {
        if (t < o) sh[t] += sh[t + o];
        if (o <= 128 && t < o) sh_ss[t] += sh_ss[t + o];
        __syncthreads();
    }
    if (t == 0) {
        const double N = (double)N_DIM;
        double mean_d2 = 2.0 * sh[0] / N - 2.0 * sh_ss[0] / (N * N);
        g_inv = (float)(1.0 / (2.0 * mean_d2));  // ALPHA = 1
    }
}

// ---------------- kernel 3: fused symmetric GEMM + d2 + exp (pipelined) -------
// 512 threads, 4x4 warp grid, 32x32 warp tile. K in 4 chunks of 64, 2-stage
// cp.async pipeline. Stage = A(128x64 bf16, 144 B/row) + B same = 36864 B;
// two stages = 73728 B, reused as fp32 transpose buffer (128 x 132 = 67584 B).
#define NTHREADS   512
#define CHUNK_K    64
#define NCHUNK     (D_DIM / CHUNK_K)     // 4
#define CROW_BYTES 144
#define STAGE_A_BYTES (TILE * CROW_BYTES)         // 18432
#define STAGE_BYTES   (2 * STAGE_A_BYTES)         // 36864
#define GEMM_SMEM     (2 * STAGE_BYTES)           // 73728
#define T_ST 132

__global__ __launch_bounds__(NTHREADS, 1)
void gemm_fused_kernel(float* __restrict__ d_out) {
    extern __shared__ char smem[];
    const uint32_t smem_u = smem_to_u32(smem);

    const int tid  = threadIdx.x;
    const int wid  = tid >> 5;
    const int lane = tid & 31;

    // decode upper-triangular tile index
    int b = blockIdx.x, ti = 0, rem = GRID_TILES;
    while (b >= rem) { b -= rem; rem--; ti++; }
    const int tj = ti + b;
    const bool diag = (ti == tj);
    const int row0 = ti * TILE;
    const int col0 = tj * TILE;

    const __nv_bfloat16* gA = g_xb + (size_t)row0 * D_DIM;
    const __nv_bfloat16* gB = g_xb + (size_t)col0 * D_DIM;

    auto load_chunk = [&](int c, int stage) {
        const uint32_t sA = smem_u + stage * STAGE_BYTES;
        const uint32_t sB = sA + STAGE_A_BYTES;
        #pragma unroll
        for (int it = 0; it < 2; it++) {
            int idx = tid + it * NTHREADS;
            int r = idx >> 3, q = idx & 7;
            uint32_t soff = (uint32_t)r * CROW_BYTES + (uint32_t)q * 16;
            size_t goff = (size_t)r * D_DIM + c * CHUNK_K + q * 8;
            CP_ASYNC_16(sA + soff, gA + goff);
            CP_ASYNC_16(sB + soff, gB + goff);
        }
        CP_ASYNC_COMMIT();
    };

    // warp tiling: 4 warps along M, 4 along N; warp tile 32x32
    const int warp_m = wid & 3;
    const int warp_n = wid >> 2;
    const int m0 = warp_m * 32;
    const int n0 = warp_n * 32;

    float acc[2][4][4];
    #pragma unroll
    for (int mi = 0; mi < 2; mi++)
        #pragma unroll
        for (int ni = 0; ni < 4; ni++)
            #pragma unroll
            for (int q = 0; q < 4; q++) acc[mi][ni][q] = 0.f;

    const uint32_t a_row = (uint32_t)(lane & 15);
    const uint32_t a_kof = (uint32_t)((lane >> 4) << 3);
    const uint32_t b_row = (uint32_t)(((lane >> 4) << 3) + (lane & 7));
    const uint32_t b_kof = (uint32_t)(((lane >> 3) & 1) << 3);

    load_chunk(0, 0);

    #pragma unroll
    for (int c = 0; c < NCHUNK; c++) {
        const int stage = c & 1;
        if (c + 1 < NCHUNK) load_chunk(c + 1, (c + 1) & 1);
        if (c + 1 < NCHUNK) { CP_ASYNC_WAIT(1); } else { CP_ASYNC_WAIT(0); }
        __syncthreads();

        const uint32_t As_u = smem_u + stage * STAGE_BYTES;
        const uint32_t Bs_u = As_u + STAGE_A_BYTES;

        #pragma unroll
        for (int ks = 0; ks < CHUNK_K / 16; ks++) {
            const uint32_t kbase = (uint32_t)ks * 32;
            uint32_t aa[2][4];
            #pragma unroll
            for (int mi = 0; mi < 2; mi++) {
                uint32_t addr = As_u + (m0 + mi * 16 + a_row) * CROW_BYTES + kbase + a_kof * 2;
                ldsm_x4(aa[mi], addr);
            }
            uint32_t bb[2][4];
            #pragma unroll
            for (int nb = 0; nb < 2; nb++) {
                uint32_t addr = Bs_u + (n0 + nb * 16 + b_row) * CROW_BYTES + kbase + b_kof * 2;
                ldsm_x4(bb[nb], addr);
            }
            #pragma unroll
            for (int mi = 0; mi < 2; mi++)
                #pragma unroll
                for (int ni = 0; ni < 4; ni++) {
                    int nb = ni >> 1, hi = ni & 1;
                    mma_16816_bf16(acc[mi][ni], aa[mi], bb[nb][hi * 2], bb[nb][hi * 2 + 1]);
                }
        }
        __syncthreads();   // stage consumed; next iteration may overwrite it
    }

    // ---- fused epilogue: d2 = sqi + sqj - 2*gram, clamp, exp, store ----
    const float inv = g_inv;
    float* trans = reinterpret_cast<float*>(smem);

    #pragma unroll
    for (int mi = 0; mi < 2; mi++) {
        const int rl0 = m0 + mi * 16 + (lane >> 2);   // local row (0..127)
        const int gi  = row0 + rl0;
        const float sqi0 = g_sq[gi];
        const float sqi8 = g_sq[gi + 8];
        #pragma unroll
        for (int ni = 0; ni < 4; ni++) {
            const int cl = n0 + ni * 8 + ((lane & 3) << 1);  // local col (0..127)
            const int gj = col0 + cl;
            const float2 sj = *reinterpret_cast<const float2*>(&g_sq[gj]);
            float e0 = __expf(-fmaxf(sqi0 + sj.x - 2.f * acc[mi][ni][0], 0.f) * inv);
            float e1 = __expf(-fmaxf(sqi0 + sj.y - 2.f * acc[mi][ni][1], 0.f) * inv);
            float e2 = __expf(-fmaxf(sqi8 + sj.x - 2.f * acc[mi][ni][2], 0.f) * inv);
            float e3 = __expf(-fmaxf(sqi8 + sj.y - 2.f * acc[mi][ni][3], 0.f) * inv);
            *reinterpret_cast<float2*>(&d_out[(size_t)gi * N_DIM + gj])       = make_float2(e0, e1);
            *reinterpret_cast<float2*>(&d_out[(size_t)(gi + 8) * N_DIM + gj]) = make_float2(e2, e3);
            if (!diag) {
                trans[(cl)     * T_ST + rl0]     = e0;
                trans[(cl + 1) * T_ST + rl0]     = e1;
                trans[(cl)     * T_ST + rl0 + 8] = e2;
                trans[(cl + 1) * T_ST + rl0 + 8] = e3;
            }
        }
    }

    if (!diag) {
        __syncthreads();
        // coalesced mirror store: tile [col0..col0+127] x [row0..row0+127]
        #pragma unroll
        for (int it = 0; it < 8; it++) {
            int e4 = tid + it * NTHREADS;  // 4096 float4s
            int r  = e4 >> 5;              // global row = col0 + r
            int c4 = e4 & 31;
            const float* src = &trans[r * T_ST + c4 * 4];
            float4 v = make_float4(src[0], src[1], src[2], src[3]);
            *reinterpret_cast<float4*>(&d_out[(size_t)(col0 + r) * N_DIM + row0 + c4 * 4]) = v;
        }
    }
}

// ---------------- launcher ----------------
extern "C" void kernel_launch(void* const* d_in, const int* in_sizes, int n_in,
                              void* d_out, int out_size) {
    const float* x = (const float*)d_in[0];
    float* out = (float*)d_out;

    static bool attr_set = false;
    if (!attr_set) {
        cudaFuncSetAttribute(gemm_fused_kernel,
                             cudaFuncAttributeMaxDynamicSharedMemorySize, GEMM_SMEM);
        attr_set = true;
    }

    prep_kernel<<<512, 256>>>(x);
    sigma_kernel<<<1, 1024>>>();
    gemm_fused_kernel<<<NUM_UTILES, NTHREADS, GEMM_SMEM>>>(out);
}

// round 8
// speedup vs baseline: 1.6659x; 1.1967x over previous
#include <cuda_runtime.h>
#include <cuda_bf16.h>
#include <cstdint>

#define N_DIM 4096
#define D_DIM 256
#define TILE  128
#define GRID_TILES (N_DIM / TILE)       // 32
#define NUM_STRIPS (GRID_TILES / 2)     // 16 strips of 256 rows
#define NUM_CTAS   272                  // sum_{i=0..15} (32 - 2i)

// ---------------- device scratch ----------------
__device__ __nv_bfloat16 g_xb[N_DIM * D_DIM];     // 2 MB bf16 copy of x
__device__ float g_sq[N_DIM];                      // row squared norms
__device__ float g_svec_partial[256][D_DIM];       // colsum partials
__device__ float g_inv;                            // 1 / (2 * sigma^2)

// ---------------- helpers ----------------
__device__ __forceinline__ uint32_t smem_to_u32(const void* p) {
    uint32_t a;
    asm("{ .reg .u64 t; cvta.to.shared.u64 t, %1; cvt.u32.u64 %0, t; }" : "=r"(a) : "l"(p));
    return a;
}

__device__ __forceinline__ void ldsm_x4(uint32_t r[4], uint32_t addr) {
    asm volatile("ldmatrix.sync.aligned.m8n8.x4.shared.b16 {%0,%1,%2,%3}, [%4];"
                 : "=r"(r[0]), "=r"(r[1]), "=r"(r[2]), "=r"(r[3]) : "r"(addr));
}

__device__ __forceinline__ void mma_16816_bf16(float c[4], const uint32_t a[4],
                                               uint32_t b0, uint32_t b1) {
    asm volatile(
        "mma.sync.aligned.m16n8k16.row.col.f32.bf16.bf16.f32 "
        "{%0,%1,%2,%3}, {%4,%5,%6,%7}, {%8,%9}, {%0,%1,%2,%3};"
        : "+f"(c[0]), "+f"(c[1]), "+f"(c[2]), "+f"(c[3])
        : "r"(a[0]), "r"(a[1]), "r"(a[2]), "r"(a[3]), "r"(b0), "r"(b1));
}

#define CP_ASYNC_16(dst, src) \
    asm volatile("cp.async.cg.shared.global [%0], [%1], 16;" :: "r"(dst), "l"(src))
#define CP_ASYNC_COMMIT() asm volatile("cp.async.commit_group;" ::: "memory")
#define CP_ASYNC_WAIT(n)  asm volatile("cp.async.wait_group %0;" :: "n"(n) : "memory")

// ---------------- kernel 1: bf16 convert + row norms + colsum partials --------
__global__ void prep_kernel(const float* __restrict__ x) {
    const int tid  = threadIdx.x;            // 256 threads, 256 blocks
    const int wid  = tid >> 5;
    const int lane = tid & 31;
    const int r0   = (blockIdx.x * 8 + wid) * 2;   // warp handles rows r0, r0+1

    {
        const float4* rowA = reinterpret_cast<const float4*>(x + (size_t)r0 * D_DIM);
        const float4* rowB = reinterpret_cast<const float4*>(x + (size_t)(r0 + 1) * D_DIM);
        uint2* dstA = reinterpret_cast<uint2*>(g_xb + (size_t)r0 * D_DIM);
        uint2* dstB = reinterpret_cast<uint2*>(g_xb + (size_t)(r0 + 1) * D_DIM);
        float s0 = 0.f, s1 = 0.f;
        #pragma unroll
        for (int i = 0; i < 2; i++) {
            float4 va = rowA[lane + i * 32];
            float4 vb = rowB[lane + i * 32];
            s0 += va.x * va.x + va.y * va.y + va.z * va.z + va.w * va.w;
            s1 += vb.x * vb.x + vb.y * vb.y + vb.z * vb.z + vb.w * vb.w;
            __nv_bfloat162 alo = __float22bfloat162_rn(make_float2(va.x, va.y));
            __nv_bfloat162 ahi = __float22bfloat162_rn(make_float2(va.z, va.w));
            __nv_bfloat162 blo = __float22bfloat162_rn(make_float2(vb.x, vb.y));
            __nv_bfloat162 bhi = __float22bfloat162_rn(make_float2(vb.z, vb.w));
            dstA[lane + i * 32] = make_uint2(*reinterpret_cast<uint32_t*>(&alo),
                                             *reinterpret_cast<uint32_t*>(&ahi));
            dstB[lane + i * 32] = make_uint2(*reinterpret_cast<uint32_t*>(&blo),
                                             *reinterpret_cast<uint32_t*>(&bhi));
        }
        #pragma unroll
        for (int o = 16; o; o >>= 1) {
            s0 += __shfl_xor_sync(0xffffffffu, s0, o);
            s1 += __shfl_xor_sync(0xffffffffu, s1, o);
        }
        if (lane == 0) { g_sq[r0] = s0; g_sq[r0 + 1] = s1; }
    }
    // colsum partial over this block's 16 rows
    const float* base = x + (size_t)blockIdx.x * 16 * D_DIM + tid;
    float acc = 0.f;
    #pragma unroll
    for (int r = 0; r < 16; r++) acc += base[r * D_DIM];
    g_svec_partial[blockIdx.x][tid] = acc;
}

// ---------------- kernel 2: sigma -> g_inv ----------------
__global__ void sigma_kernel() {
    const int t   = threadIdx.x;      // 1024 threads
    const int col = t & 255;
    const int grp = t >> 8;           // 4 groups of 64 partial-rows

    float scp = 0.f;
    #pragma unroll 8
    for (int b = grp * 64; b < grp * 64 + 64; b++) scp += g_svec_partial[b][col];

    __shared__ float sh_sc[4][256];
    sh_sc[grp][col] = scp;

    double sq = 0.0;
    #pragma unroll
    for (int k = 0; k < 4; k++) sq += (double)g_sq[t + k * 1024];

    __shared__ double sh[1024];
    sh[t] = sq;
    __syncthreads();

    __shared__ double sh_ss[256];
    if (t < 256) {
        double sc = (double)sh_sc[0][t] + (double)sh_sc[1][t]
                  + (double)sh_sc[2][t] + (double)sh_sc[3][t];
        sh_ss[t] = sc * sc;
    }
    __syncthreads();

    for (int o = 512; o; o >>= 1) {
        if (t < o) sh[t] += sh[t + o];
        if (o <= 128 && t < o) sh_ss[t] += sh_ss[t + o];
        __syncthreads();
    }
    if (t == 0) {
        const double N = (double)N_DIM;
        double mean_d2 = 2.0 * sh[0] / N - 2.0 * sh_ss[0] / (N * N);
        g_inv = (float)(1.0 / (2.0 * mean_d2));  // ALPHA = 1
    }
}

// ---------------- kernel 3: fused symmetric GEMM + d2 + exp -------------------
// CTA tile 256x128 (A rows 256, B rows 128). 512 threads: 4x4 warps, warp tile
// 64x32. K in 4 chunks of 64, 3-stage cp.async pipeline, ONE sync per chunk.
#define NTHREADS   512
#define CHUNK_K    64
#define NCHUNK     (D_DIM / CHUNK_K)     // 4
#define NSTAGE     3
#define CROW_BYTES 144
#define A_ROWS     256
#define B_ROWS     128
#define SA_BYTES   (A_ROWS * CROW_BYTES)          // 36864
#define SB_BYTES   (B_ROWS * CROW_BYTES)          // 18432
#define STAGE_BYTES (SA_BYTES + SB_BYTES)         // 55296
#define GEMM_SMEM  (NSTAGE * STAGE_BYTES)         // 165888
#define T_ST 132                                   // transpose buffer stride

__global__ __launch_bounds__(NTHREADS, 1)
void gemm_fused_kernel(float* __restrict__ d_out) {
    extern __shared__ char smem[];
    const uint32_t smem_u = smem_to_u32(smem);

    const int tid  = threadIdx.x;
    const int wid  = tid >> 5;
    const int lane = tid & 31;

    // decode (strip i, col tile j): strip i has 32-2i tiles, j = 2i + b
    int b = blockIdx.x, si = 0, rem = 32;
    while (b >= rem) { b -= rem; rem -= 2; si++; }
    const int j = 2 * si + b;
    const int row0 = si * 256;          // A strip base
    const int col0 = j * TILE;          // B tile base
    const bool mirror = (j >= 2 * si + 2);

    const __nv_bfloat16* gA = g_xb + (size_t)row0 * D_DIM;
    const __nv_bfloat16* gB = g_xb + (size_t)col0 * D_DIM;

    auto load_chunk = [&](int c, int stage) {
        const uint32_t sA = smem_u + stage * STAGE_BYTES;
        const uint32_t sB = sA + SA_BYTES;
        // A: 2048 16B chunks (it 0..3), B: 1024 (it 4..5)
        #pragma unroll
        for (int it = 0; it < 4; it++) {
            int idx = tid + it * NTHREADS;
            int r = idx >> 3, q = idx & 7;
            CP_ASYNC_16(sA + (uint32_t)r * CROW_BYTES + (uint32_t)q * 16,
                        gA + (size_t)r * D_DIM + c * CHUNK_K + q * 8);
        }
        #pragma unroll
        for (int it = 0; it < 2; it++) {
            int idx = tid + it * NTHREADS;
            int r = idx >> 3, q = idx & 7;
            CP_ASYNC_16(sB + (uint32_t)r * CROW_BYTES + (uint32_t)q * 16,
                        gB + (size_t)r * D_DIM + c * CHUNK_K + q * 8);
        }
        CP_ASYNC_COMMIT();
    };

    // warp tiling: warp_m in 0..3 (64 rows each), warp_n in 0..3 (32 cols each)
    const int warp_m = wid & 3;
    const int warp_n = wid >> 2;
    const int m0 = warp_m * 64;
    const int n0 = warp_n * 32;

    float acc[4][4][4];
    #pragma unroll
    for (int mi = 0; mi < 4; mi++)
        #pragma unroll
        for (int ni = 0; ni < 4; ni++)
            #pragma unroll
            for (int q = 0; q < 4; q++) acc[mi][ni][q] = 0.f;

    const uint32_t a_row = (uint32_t)(lane & 15);
    const uint32_t a_kof = (uint32_t)((lane >> 4) << 3);
    const uint32_t b_row = (uint32_t)(((lane >> 4) << 3) + (lane & 7));
    const uint32_t b_kof = (uint32_t)(((lane >> 3) & 1) << 3);

    load_chunk(0, 0);

    #pragma unroll
    for (int c = 0; c < NCHUNK; c++) {
        const int stage = c % NSTAGE;
        if (c + 1 < NCHUNK) { load_chunk(c + 1, (c + 1) % NSTAGE); CP_ASYNC_WAIT(1); }
        else                { CP_ASYNC_WAIT(0); }
        __syncthreads();   // single barrier per chunk (3-stage buffering makes this safe)

        const uint32_t As_u = smem_u + stage * STAGE_BYTES;
        const uint32_t Bs_u = As_u + SA_BYTES;

        #pragma unroll
        for (int ks = 0; ks < CHUNK_K / 16; ks++) {
            const uint32_t kbase = (uint32_t)ks * 32;
            uint32_t bbf[2][4];
            #pragma unroll
            for (int nb = 0; nb < 2; nb++) {
                uint32_t addr = Bs_u + (n0 + nb * 16 + b_row) * CROW_BYTES + kbase + b_kof * 2;
                ldsm_x4(bbf[nb], addr);
            }
            #pragma unroll
            for (int mi = 0; mi < 4; mi++) {
                uint32_t aa[4];
                uint32_t addr = As_u + (m0 + mi * 16 + a_row) * CROW_BYTES + kbase + a_kof * 2;
                ldsm_x4(aa, addr);
                #pragma unroll
                for (int ni = 0; ni < 4; ni++) {
                    int nb = ni >> 1, hi = ni & 1;
                    mma_16816_bf16(acc[mi][ni], aa, bbf[nb][hi * 2], bbf[nb][hi * 2 + 1]);
                }
            }
        }
    }
    __syncthreads();   // all MMAs done before smem is reused as transpose buffer

    // ---- epilogue: e = exp(-(sqi+sqj-2g)/2s^2); direct store; keep e in acc --
    const float inv = g_inv;
    #pragma unroll
    for (int mi = 0; mi < 4; mi++) {
        const int rl0 = m0 + mi * 16 + (lane >> 2);   // local row (0..255)
        const int gi  = row0 + rl0;
        const float sqi0 = g_sq[gi];
        const float sqi8 = g_sq[gi + 8];
        #pragma unroll
        for (int ni = 0; ni < 4; ni++) {
            const int cl = n0 + ni * 8 + ((lane & 3) << 1);
            const int gj = col0 + cl;
            const float2 sj = *reinterpret_cast<const float2*>(&g_sq[gj]);
            float e0 = __expf(-fmaxf(sqi0 + sj.x - 2.f * acc[mi][ni][0], 0.f) * inv);
            float e1 = __expf(-fmaxf(sqi0 + sj.y - 2.f * acc[mi][ni][1], 0.f) * inv);
            float e2 = __expf(-fmaxf(sqi8 + sj.x - 2.f * acc[mi][ni][2], 0.f) * inv);
            float e3 = __expf(-fmaxf(sqi8 + sj.y - 2.f * acc[mi][ni][3], 0.f) * inv);
            *reinterpret_cast<float2*>(&d_out[(size_t)gi * N_DIM + gj])       = make_float2(e0, e1);
            *reinterpret_cast<float2*>(&d_out[(size_t)(gi + 8) * N_DIM + gj]) = make_float2(e2, e3);
            acc[mi][ni][0] = e0; acc[mi][ni][1] = e1;
            acc[mi][ni][2] = e2; acc[mi][ni][3] = e3;
        }
    }

    // ---- mirror store in two 128-row phases through smem transpose buffer ----
    if (mirror) {
        float* trans = reinterpret_cast<float*>(smem);
        #pragma unroll
        for (int p = 0; p < 2; p++) {
            if ((warp_m >> 1) == p) {
                const int rh_base = (warp_m & 1) * 64 + (lane >> 2);
                #pragma unroll
                for (int mi = 0; mi < 4; mi++) {
                    const int rh = rh_base + mi * 16;
                    #pragma unroll
                    for (int ni = 0; ni < 4; ni++) {
                        const int cl = n0 + ni * 8 + ((lane & 3) << 1);
                        trans[(cl)     * T_ST + rh]     = acc[mi][ni][0];
                        trans[(cl + 1) * T_ST + rh]     = acc[mi][ni][1];
                        trans[(cl)     * T_ST + rh + 8] = acc[mi][ni][2];
                        trans[(cl + 1) * T_ST + rh + 8] = acc[mi][ni][3];
                    }
                }
            }
            __syncthreads();
            // coalesced: 128 rows (col0+r) x 128 cols (row0 + p*128 + ...)
            #pragma unroll
            for (int it = 0; it < 8; it++) {
                int e4 = tid + it * NTHREADS;   // 4096 float4
                int r  = e4 >> 5;
                int c4 = e4 & 31;
                const float* src = &trans[r * T_ST + c4 * 4];
                float4 v = make_float4(src[0], src[1], src[2], src[3]);
                *reinterpret_cast<float4*>(
                    &d_out[(size_t)(col0 + r) * N_DIM + row0 + p * 128 + c4 * 4]) = v;
            }
            __syncthreads();
        }
    }
}

// ---------------- launcher ----------------
extern "C" void kernel_launch(void* const* d_in, const int* in_sizes, int n_in,
                              void* d_out, int out_size) {
    const float* x = (const float*)d_in[0];
    float* out = (float*)d_out;

    static bool attr_set = false;
    if (!attr_set) {
        cudaFuncSetAttribute(gemm_fused_kernel,
                             cudaFuncAttributeMaxDynamicSharedMemorySize, GEMM_SMEM);
        attr_set = true;
    }

    prep_kernel<<<256, 256>>>(x);
    sigma_kernel<<<1, 1024>>>();
    gemm_fused_kernel<<<NUM_CTAS, NTHREADS, GEMM_SMEM>>>(out);
}